// round 16
// baseline (speedup 1.0000x reference)
#include <cuda_runtime.h>
#include <cuda_fp16.h>
#include <cstdint>

#define NN   50000
#define INF  128
#define HF   256
#define NE   800000
#define KTOT 256

// ---------------- scratch (static device globals; no allocation) -------------
__device__ int   d_is64;
__device__ int   d_deg[NN];
__device__ int   d_rowptr[NN + 1];
__device__ int   d_cursor[NN];
__device__ int   d_csrc[NE];
__device__ __align__(16) __half d_xh[NN * INF];    // x in fp16
__device__ __align__(16) __half d_Ah[NN * KTOT];   // [agg1 | x] fp16
__device__ __align__(16) __half d_Wh[HF * KTOT];   // Wcat fp16 (n-major, k contig)
__device__ float d_p[NN];
__device__ float d_q[NN];
__device__ int   d_pref[64];
__device__ int   d_flag[64];

__device__ __forceinline__ int edge_at(const void* ei, long long idx) {
    if (d_is64) return (int)((const long long*)ei)[idx];
    return ((const int*)ei)[idx];
}

// ---------------- [1] init: zero deg/flags + detect + W prep + x->fp16 -------
__global__ void k_init(const int* __restrict__ ei32, const float* __restrict__ x,
                       const float* __restrict__ W1l, const float* __restrict__ W1r) {
    int t = blockIdx.x * blockDim.x + threadIdx.x;   // 65536 threads
    if (t == 0) {
        int all0 = 1;
        for (int i = 0; i < 32; i++)
            if (ei32[2 * i + 1] != 0) { all0 = 0; break; }
        d_is64 = all0;
    }
    if (t < NN) d_deg[t] = 0;
    if (t < 64) { d_flag[t] = 0; d_pref[t] = 0; }
    if (t < HF * KTOT) {
        int n = t >> 8, k = t & 255;
        float w = (k < 128) ? W1l[n * 128 + k] : W1r[n * 128 + (k - 128)];
        d_Wh[t] = __float2half_rn(w);
    }
    const int NG = NN * INF / 4;
    for (int i = t; i < NG; i += 65536) {
        float4 v = reinterpret_cast<const float4*>(x)[i];
        __half2 a = make_half2(__float2half_rn(v.x), __float2half_rn(v.y));
        __half2 b = make_half2(__float2half_rn(v.z), __float2half_rn(v.w));
        uint2 r;
        r.x = *reinterpret_cast<uint32_t*>(&a);
        r.y = *reinterpret_cast<uint32_t*>(&b);
        reinterpret_cast<uint2*>(d_xh)[i] = r;
    }
}

// ---------------- [2] count degrees (4 edges/thread for MLP) -----------------
__global__ void k_count(const void* __restrict__ ei) {
    int e0 = (blockIdx.x * blockDim.x + threadIdx.x) * 4;
#pragma unroll
    for (int i = 0; i < 4; i++) {
        int e = e0 + i;
        if (e < NE) {
            int dst = edge_at(ei, (long long)NE + e);
            if ((unsigned)dst < NN) atomicAdd(&d_deg[dst], 1);
        }
    }
}

// ---------------- [3] single-pass chained scan (49 blocks, all wave-1) -------
__global__ void __launch_bounds__(256, 1) k_scan() {
    __shared__ int sh[256];
    __shared__ int s_pref;
    int t = threadIdx.x;
    int b = blockIdx.x;
    int base = b * 1024 + t * 4;
    int v[4];
#pragma unroll
    for (int i = 0; i < 4; i++) {
        int idx = base + i;
        v[i] = (idx < NN) ? d_deg[idx] : 0;
    }
    int s = v[0] + v[1] + v[2] + v[3];
    sh[t] = s;
    __syncthreads();
    for (int off = 1; off < 256; off <<= 1) {
        int x_ = (t >= off) ? sh[t - off] : 0;
        __syncthreads();
        sh[t] += x_;
        __syncthreads();
    }
    int run = sh[t] - s;          // block-local exclusive prefix
    int total = sh[255];
    if (t == 0) {
        int pref = 0;
        if (b > 0) {
            while (atomicAdd(&d_flag[b - 1], 0) == 0) {}
            __threadfence();
            pref = d_pref[b - 1];
        }
        d_pref[b] = pref + total;
        __threadfence();
        atomicExch(&d_flag[b], 1);
        s_pref = pref;
        if (b == 0) d_rowptr[NN] = NE;
    }
    __syncthreads();
    run += s_pref;
#pragma unroll
    for (int i = 0; i < 4; i++) {
        int idx = base + i;
        if (idx < NN) {
            d_rowptr[idx] = run;
            d_cursor[idx] = run;
        }
        run += v[i];
    }
}

// ---------------- [4] fill CSR (4 edges/thread for MLP) ----------------------
__global__ void k_fill(const void* __restrict__ ei) {
    int e0 = (blockIdx.x * blockDim.x + threadIdx.x) * 4;
#pragma unroll
    for (int i = 0; i < 4; i++) {
        int e = e0 + i;
        if (e < NE) {
            int dst = edge_at(ei, (long long)NE + e);
            int src = edge_at(ei, e);
            if ((unsigned)dst < NN && (unsigned)src < NN) {
                int pos = atomicAdd(&d_cursor[dst], 1);
                if ((unsigned)pos < NE) d_csrc[pos] = src;
            }
        }
    }
}

// ---------------- [5] aggregation 1 (fp16 gather) + pack A=[agg1|x] ----------
__global__ void k_agg1() {
    int warp = threadIdx.x >> 5;
    int lane = threadIdx.x & 31;
    int n = blockIdx.x * 8 + warp;
    if (n >= NN) return;

    int s = d_rowptr[n], e = d_rowptr[n + 1];
    float4 acc = make_float4(0.f, 0.f, 0.f, 0.f);
    for (int j = s; j < e; j++) {
        int src = d_csrc[j];
        uint2 v = reinterpret_cast<const uint2*>(d_xh + (size_t)src * INF)[lane];
        float2 f0 = __half22float2(*reinterpret_cast<__half2*>(&v.x));
        float2 f1 = __half22float2(*reinterpret_cast<__half2*>(&v.y));
        acc.x += f0.x; acc.y += f0.y; acc.z += f1.x; acc.w += f1.y;
    }
    int deg = e - s;
    float inv = 1.f / (float)max(deg, 1);
    __half2 a = make_half2(__float2half_rn(acc.x * inv), __float2half_rn(acc.y * inv));
    __half2 b = make_half2(__float2half_rn(acc.z * inv), __float2half_rn(acc.w * inv));
    uint2 m;
    m.x = *reinterpret_cast<uint32_t*>(&a);
    m.y = *reinterpret_cast<uint32_t*>(&b);

    size_t rb = (size_t)n * KTOT;
    reinterpret_cast<uint2*>(d_Ah + rb)[lane] = m;
    reinterpret_cast<uint2*>(d_Ah + rb + 128)[lane] =
        reinterpret_cast<const uint2*>(d_xh + (size_t)n * INF)[lane];
}

// ---------------- [6] cp.async double-buffered fp16 GEMM + fused epilogue ----
#define SM_BIAS 0
#define SM_W2L  1024
#define SM_W2R  2048
#define SM_PQ   3072
#define SM_DATA 5120
#define OFF_A   0
#define OFF_B   18432
#define STAGE   55296
#define SM_TOT  (SM_DATA + 2 * STAGE)   // 115712

__device__ __forceinline__ uint32_t smem_u32(const void* p) {
    uint32_t a;
    asm("{ .reg .u64 t; cvta.to.shared.u64 t, %1; cvt.u32.u64 %0, t; }" : "=r"(a) : "l"(p));
    return a;
}
__device__ __forceinline__ void cp16(uint32_t dst, const void* src, int sz) {
    asm volatile("cp.async.cg.shared.global [%0], [%1], 16, %2;"
                 :: "r"(dst), "l"(src), "r"(sz) : "memory");
}
__device__ __forceinline__ void cp_commit() {
    asm volatile("cp.async.commit_group;" ::: "memory");
}
template <int N>
__device__ __forceinline__ void cp_wait() {
    asm volatile("cp.async.wait_group %0;" :: "n"(N) : "memory");
}
__device__ __forceinline__ void ldsm4(uint32_t& r0, uint32_t& r1, uint32_t& r2,
                                      uint32_t& r3, uint32_t addr) {
    asm volatile("ldmatrix.sync.aligned.m8n8.x4.shared.b16 {%0,%1,%2,%3}, [%4];"
                 : "=r"(r0), "=r"(r1), "=r"(r2), "=r"(r3) : "r"(addr));
}
__device__ __forceinline__ void mma16816(float* c, uint32_t a0, uint32_t a1,
                                         uint32_t a2, uint32_t a3,
                                         uint32_t b0, uint32_t b1) {
    asm volatile(
        "mma.sync.aligned.m16n8k16.row.col.f32.f16.f16.f32 "
        "{%0,%1,%2,%3},{%4,%5,%6,%7},{%8,%9},{%0,%1,%2,%3};"
        : "+f"(c[0]), "+f"(c[1]), "+f"(c[2]), "+f"(c[3])
        : "r"(a0), "r"(a1), "r"(a2), "r"(a3), "r"(b0), "r"(b1));
}

__device__ __forceinline__ void issue_chunk(uint32_t sb, int t, int rowbase,
                                            int ch, int s) {
    int kbase = ch * 64;
    uint32_t base = sb + SM_DATA + s * STAGE;
#pragma unroll
    for (int i = 0; i < 2; i++) {              // A: 1024 x 16B
        int v = t + i * 512;
        int row = v >> 3, kg = v & 7;
        int gr = rowbase + row;
        int sz = (gr < NN) ? 16 : 0;
        size_t go = (size_t)gr * KTOT + kbase + kg * 8;
        uint32_t so = (uint32_t)(row * 144 + kg * 16);
        cp16(base + OFF_A + so, d_Ah + go, sz);
    }
#pragma unroll
    for (int i = 0; i < 4; i++) {              // B: 2048 x 16B
        int v = t + i * 512;
        int row = v >> 3, kg = v & 7;
        size_t go = (size_t)row * KTOT + kbase + kg * 8;
        uint32_t so = (uint32_t)(row * 144 + kg * 16);
        cp16(base + OFF_B + so, d_Wh + go, 16);
    }
    cp_commit();
}

__global__ void __launch_bounds__(512, 1)
k_gemm(const float* __restrict__ b1, const float* __restrict__ W2l,
       const float* __restrict__ W2r) {
    extern __shared__ char smem[];
    uint32_t sb = smem_u32(smem);
    int t = threadIdx.x;
    int wid = t >> 5;
    int lane = t & 31;
    int g = lane >> 2;
    int tq = lane & 3;
    int wm = wid & 7;
    int wn = wid >> 3;
    int rowbase = blockIdx.x * 128;

    if (t < 256) {
        *reinterpret_cast<float*>(smem + SM_BIAS + t * 4) = b1[t];
        *reinterpret_cast<float*>(smem + SM_W2L + t * 4) = W2l[t];
        *reinterpret_cast<float*>(smem + SM_W2R + t * 4) = W2r[t];
    }

    float acc[64];
#pragma unroll
    for (int i = 0; i < 64; i++) acc[i] = 0.f;

    int arow = wm * 16 + (lane & 15);
    uint32_t a_off = (uint32_t)(arow * 144 + ((lane >> 4) & 1) * 16);
    int bro = (lane >> 4) & 1;
    uint32_t b_off = (uint32_t)(((lane & 7) + bro * 8) * 144 + ((lane >> 3) & 1) * 16);

    issue_chunk(sb, t, rowbase, 0, 0);

    for (int ch = 0; ch < 4; ch++) {
        if (ch < 3) {
            issue_chunk(sb, t, rowbase, ch + 1, (ch + 1) & 1);
            cp_wait<1>();
        } else {
            cp_wait<0>();
        }
        __syncthreads();

        uint32_t stbase = sb + SM_DATA + (ch & 1) * STAGE;
#pragma unroll
        for (int ks = 0; ks < 4; ks++) {
            uint32_t ksb = (uint32_t)(ks * 32);
            uint32_t a0, a1, a2, a3;
            ldsm4(a0, a1, a2, a3, stbase + OFF_A + a_off + ksb);
#pragma unroll
            for (int jp = 0; jp < 8; jp++) {
                uint32_t brow = (uint32_t)((wn * 128 + jp * 16) * 144);
                uint32_t b0, b1v, b2v, b3;
                ldsm4(b0, b1v, b2v, b3, stbase + OFF_B + brow + b_off + ksb);
                mma16816(acc + jp * 8, a0, a1, a2, a3, b0, b1v);
                mma16816(acc + jp * 8 + 4, a0, a1, a2, a3, b2v, b3);
            }
        }
        __syncthreads();
    }

    const float* s_bias = reinterpret_cast<const float*>(smem + SM_BIAS);
    const float* s_w2l = reinterpret_cast<const float*>(smem + SM_W2L);
    const float* s_w2r = reinterpret_cast<const float*>(smem + SM_W2R);
    float p1 = 0.f, q1 = 0.f, p2 = 0.f, q2 = 0.f;
#pragma unroll
    for (int j = 0; j < 16; j++) {
        int c0 = wn * 128 + j * 8 + 2 * tq;
        float v00 = acc[j * 4 + 0] + s_bias[c0];
        float v01 = acc[j * 4 + 1] + s_bias[c0 + 1];
        float v10 = acc[j * 4 + 2] + s_bias[c0];
        float v11 = acc[j * 4 + 3] + s_bias[c0 + 1];
        v00 = v00 > 0.f ? v00 : 0.f;
        v01 = v01 > 0.f ? v01 : 0.f;
        v10 = v10 > 0.f ? v10 : 0.f;
        v11 = v11 > 0.f ? v11 : 0.f;
        p1 = fmaf(v00, s_w2l[c0], fmaf(v01, s_w2l[c0 + 1], p1));
        q1 = fmaf(v00, s_w2r[c0], fmaf(v01, s_w2r[c0 + 1], q1));
        p2 = fmaf(v10, s_w2l[c0], fmaf(v11, s_w2l[c0 + 1], p2));
        q2 = fmaf(v10, s_w2r[c0], fmaf(v11, s_w2r[c0 + 1], q2));
    }
#pragma unroll
    for (int off = 1; off < 4; off <<= 1) {
        p1 += __shfl_xor_sync(0xffffffffu, p1, off);
        q1 += __shfl_xor_sync(0xffffffffu, q1, off);
        p2 += __shfl_xor_sync(0xffffffffu, p2, off);
        q2 += __shfl_xor_sync(0xffffffffu, q2, off);
    }
    float* pbuf = reinterpret_cast<float*>(smem + SM_PQ);           // [2][128]
    float* qbuf = reinterpret_cast<float*>(smem + SM_PQ + 1024);    // [2][128]
    if (tq == 0) {
        int r1 = wm * 16 + g;
        pbuf[wn * 128 + r1] = p1;
        qbuf[wn * 128 + r1] = q1;
        pbuf[wn * 128 + r1 + 8] = p2;
        qbuf[wn * 128 + r1 + 8] = q2;
    }
    __syncthreads();
    if (t < 128) {
        int gr = rowbase + t;
        if (gr < NN) {
            d_p[gr] = pbuf[t] + pbuf[128 + t];
            d_q[gr] = qbuf[t] + qbuf[128 + t];
        }
    }
}

// ---------------- [7] out = mean_agg(p) + b2 + q -----------------------------
__global__ void k_out(const float* __restrict__ b2, float* __restrict__ out) {
    int warp = threadIdx.x >> 5;
    int lane = threadIdx.x & 31;
    int n = blockIdx.x * 8 + warp;
    if (n >= NN) return;

    int s = d_rowptr[n], e = d_rowptr[n + 1];
    float acc = 0.f;
    for (int j = s + lane; j < e; j += 32) acc += d_p[d_csrc[j]];
#pragma unroll
    for (int off = 16; off > 0; off >>= 1)
        acc += __shfl_down_sync(0xffffffffu, acc, off);
    if (lane == 0) {
        int deg = e - s;
        out[n] = acc / (float)max(deg, 1) + b2[0] + d_q[n];
    }
}

// ---------------- launch -----------------------------------------------------
extern "C" void kernel_launch(void* const* d_in, const int* in_sizes, int n_in,
                              void* d_out, int out_size) {
    const float* x    = (const float*)d_in[0];
    const void*  ei   = d_in[1];
    const float* W1l  = (const float*)d_in[2];
    const float* b1   = (const float*)d_in[3];
    const float* W1r  = (const float*)d_in[4];
    const float* W2l  = (const float*)d_in[5];
    const float* b2   = (const float*)d_in[6];
    const float* W2r  = (const float*)d_in[7];
    float* out = (float*)d_out;

    static int attr_set = 0;
    if (!attr_set) {
        cudaFuncSetAttribute(k_gemm, cudaFuncAttributeMaxDynamicSharedMemorySize, SM_TOT);
        attr_set = 1;
    }

    const int nb_scan = (NN + 1023) / 1024;   // 49

    k_init<<<256, 256>>>((const int*)ei, x, W1l, W1r);
    k_count<<<(NE + 1023) / 1024, 256>>>(ei);
    k_scan<<<nb_scan, 256>>>();
    k_fill<<<(NE + 1023) / 1024, 256>>>(ei);
    k_agg1<<<(NN + 7) / 8, 256>>>();
    k_gemm<<<(NN + 127) / 128, 512, SM_TOT>>>(b1, W2l, W2r);
    k_out<<<(NN + 7) / 8, 256>>>(b2, out);
}